// round 4
// baseline (speedup 1.0000x reference)
#include <cuda_runtime.h>
#include <cuda_fp16.h>
#include <cstdint>

#define N_NODES_MAX 100000
#define IN_F 128
#define OUT_F 64
#define NDIV 9
#define CAT_F (NDIV * OUT_F)   // 576

// Scratch: Wh[d][n][o] in fp16: 9*100000*64*2 = 115.2 MB (mostly L2-resident)
__device__ __half g_Whh[(size_t)NDIV * N_NODES_MAX * OUT_F];

// ---------------------------------------------------------------------------
// tf32 helpers
// ---------------------------------------------------------------------------
__device__ __forceinline__ unsigned f2tf32(float x) {
    unsigned r;
    asm("cvt.rna.tf32.f32 %0, %1;" : "=r"(r) : "f"(x));
    return r;
}

__device__ __forceinline__ uint2 split_tf32(float x) {
    unsigned h = f2tf32(x);
    unsigned l = f2tf32(x - __uint_as_float(h));
    return make_uint2(h, l);
}

__device__ __forceinline__ void mma_tf32(float c[4],
                                         unsigned a0, unsigned a1, unsigned a2, unsigned a3,
                                         unsigned b0, unsigned b1) {
    asm volatile(
        "mma.sync.aligned.m16n8k8.row.col.f32.tf32.tf32.f32 "
        "{%0,%1,%2,%3}, {%4,%5,%6,%7}, {%8,%9}, {%0,%1,%2,%3};"
        : "+f"(c[0]), "+f"(c[1]), "+f"(c[2]), "+f"(c[3])
        : "r"(a0), "r"(a1), "r"(a2), "r"(a3), "r"(b0), "r"(b1));
}

// ---------------------------------------------------------------------------
// GEMM: for all d: Wh[d, n, o] = (sum_f feature[n,f] * W[d,o,f]) * norm[n]
// One block per 128-row tile; loops over all 9 divisions internally (A tile
// loaded + tf32-split ONCE). A and B both pre-split into smem as uint2{hi,lo}
// so the mainloop is pure LDS.64 + HMMA.
// ---------------------------------------------------------------------------
#define AS 132   // uint2 stride for A rows
#define BS 132   // uint2 stride for B rows
#define GEMM_SMEM_BYTES ((128 * AS + 64 * BS) * (int)sizeof(uint2))   // 202,752 B

__global__ __launch_bounds__(256, 1)
void gemm_kernel(const float* __restrict__ feature,
                 const float* __restrict__ norm,
                 const float* __restrict__ W,
                 int n_nodes) {
    extern __shared__ uint2 smem2[];
    uint2* As2 = smem2;             // [128][AS]  pre-split A (hi,lo)
    uint2* Bp  = smem2 + 128 * AS;  // [64][BS]   pre-split B (hi,lo)

    const int row0 = blockIdx.x * 128;
    const int tid  = threadIdx.x;

    // Load + split A tile once (zero-pad past N)
    for (int i = tid; i < 128 * 32; i += 256) {
        int r = i >> 5, c4 = i & 31;
        float4 v = make_float4(0.f, 0.f, 0.f, 0.f);
        int gr = row0 + r;
        if (gr < n_nodes)
            v = *(const float4*)(feature + (size_t)gr * IN_F + c4 * 4);
        uint2* p = As2 + r * AS + c4 * 4;
        p[0] = split_tf32(v.x); p[1] = split_tf32(v.y);
        p[2] = split_tf32(v.z); p[3] = split_tf32(v.w);
    }

    const int warp = tid >> 5, lane = tid & 31;
    const int g = lane >> 2, t = lane & 3;
    const int m0 = warp * 16;
    const int r0 = row0 + m0 + g;
    const int r1 = r0 + 8;
    const float s0 = (r0 < n_nodes) ? __ldg(norm + r0) : 0.f;
    const float s1 = (r1 < n_nodes) ? __ldg(norm + r1) : 0.f;

    for (int d = 0; d < NDIV; d++) {
        __syncthreads();   // protect Bp from previous iteration's readers
        // Load + split W_d: Bp[o][f]
        for (int i = tid; i < 64 * 32; i += 256) {
            int r = i >> 5, c4 = i & 31;
            float4 v = *(const float4*)(W + ((size_t)d * OUT_F + r) * IN_F + c4 * 4);
            uint2* p = Bp + r * BS + c4 * 4;
            p[0] = split_tf32(v.x); p[1] = split_tf32(v.y);
            p[2] = split_tf32(v.z); p[3] = split_tf32(v.w);
        }
        __syncthreads();

        float acc[8][4];
#pragma unroll
        for (int nt = 0; nt < 8; nt++)
            acc[nt][0] = acc[nt][1] = acc[nt][2] = acc[nt][3] = 0.f;

#pragma unroll
        for (int ks = 0; ks < 16; ks++) {
            const int k0 = ks * 8;
            uint2 A0 = As2[(m0 + g)     * AS + k0 + t];
            uint2 A1 = As2[(m0 + g + 8) * AS + k0 + t];
            uint2 A2 = As2[(m0 + g)     * AS + k0 + t + 4];
            uint2 A3 = As2[(m0 + g + 8) * AS + k0 + t + 4];
#pragma unroll
            for (int nt = 0; nt < 8; nt++) {
                uint2 B0 = Bp[(nt * 8 + g) * BS + k0 + t];
                uint2 B1 = Bp[(nt * 8 + g) * BS + k0 + t + 4];
                // 3-pass split: hi*hi + hi*lo + lo*hi  (~fp32 accuracy)
                mma_tf32(acc[nt], A0.x, A1.x, A2.x, A3.x, B0.x, B1.x);
                mma_tf32(acc[nt], A0.x, A1.x, A2.x, A3.x, B0.y, B1.y);
                mma_tf32(acc[nt], A0.y, A1.y, A2.y, A3.y, B0.x, B1.x);
            }
        }

        // Epilogue: scale by norm, store fp16
        __half* base = g_Whh + (size_t)d * n_nodes * OUT_F;
#pragma unroll
        for (int nt = 0; nt < 8; nt++) {
            int col = nt * 8 + 2 * t;
            if (r0 < n_nodes) {
                __half2 h = __floats2half2_rn(acc[nt][0] * s0, acc[nt][1] * s0);
                *(__half2*)(base + (size_t)r0 * OUT_F + col) = h;
            }
            if (r1 < n_nodes) {
                __half2 h = __floats2half2_rn(acc[nt][2] * s1, acc[nt][3] * s1);
                *(__half2*)(base + (size_t)r1 * OUT_F + col) = h;
            }
        }
    }
}

// ---------------------------------------------------------------------------
// Scatter: out[dst, div*64 + o] += Wh[div, src, o]
// 8 threads per edge: one uint4 (8 halves) gather + 2x red.global.add.v4.
// ---------------------------------------------------------------------------
__global__ __launch_bounds__(256)
void scatter_kernel(const int* __restrict__ src,
                    const int* __restrict__ dst,
                    const int* __restrict__ ediv,
                    float* __restrict__ out,
                    int E, int n_nodes) {
    long long tt = (long long)blockIdx.x * blockDim.x + threadIdx.x;
    long long total = (long long)E * 8;
    if (tt >= total) return;
    int e = (int)(tt >> 3);
    int j = (int)(tt & 7);
    int dv = __ldg(ediv + e);
    int s  = __ldg(src + e);
    int dd = __ldg(dst + e);
    const uint4 u = *(const uint4*)(g_Whh + ((size_t)dv * n_nodes + s) * OUT_F + j * 8);
    float2 f0 = __half22float2(*(const __half2*)&u.x);
    float2 f1 = __half22float2(*(const __half2*)&u.y);
    float2 f2 = __half22float2(*(const __half2*)&u.z);
    float2 f3 = __half22float2(*(const __half2*)&u.w);
    float* p = out + (size_t)dd * CAT_F + dv * OUT_F + j * 8;
    asm volatile("red.global.add.v4.f32 [%0], {%1,%2,%3,%4};"
                 :: "l"(p), "f"(f0.x), "f"(f0.y), "f"(f1.x), "f"(f1.y) : "memory");
    asm volatile("red.global.add.v4.f32 [%0], {%1,%2,%3,%4};"
                 :: "l"(p + 4), "f"(f2.x), "f"(f2.y), "f"(f3.x), "f"(f3.y) : "memory");
}

// ---------------------------------------------------------------------------
// Finalize: out = relu(out * norm[n]), in place. float4 per thread.
// ---------------------------------------------------------------------------
__global__ __launch_bounds__(256)
void finalize_kernel(const float* __restrict__ norm,
                     float* __restrict__ out,
                     int n_nodes) {
    long long tt = (long long)blockIdx.x * blockDim.x + threadIdx.x;
    long long total = (long long)n_nodes * (CAT_F / 4);
    if (tt >= total) return;
    int n = (int)(tt / (CAT_F / 4));
    float s = __ldg(norm + n);
    float4* p = (float4*)out + tt;
    float4 v = *p;
    v.x = fmaxf(v.x * s, 0.f);
    v.y = fmaxf(v.y * s, 0.f);
    v.z = fmaxf(v.z * s, 0.f);
    v.w = fmaxf(v.w * s, 0.f);
    *p = v;
}

// ---------------------------------------------------------------------------
extern "C" void kernel_launch(void* const* d_in, const int* in_sizes, int n_in,
                              void* d_out, int out_size) {
    const float* feature = (const float*)d_in[0];
    const float* norm    = (const float*)d_in[1];
    const float* W       = (const float*)d_in[2];
    const int*   src     = (const int*)d_in[3];
    const int*   dst     = (const int*)d_in[4];
    const int*   ediv    = (const int*)d_in[5];
    float* out = (float*)d_out;

    const int n_nodes = in_sizes[1];          // norm is [N,1]
    const int E       = in_sizes[3];          // src is [E]

    static bool attr_done = false;
    if (!attr_done) {
        cudaFuncSetAttribute(gemm_kernel, cudaFuncAttributeMaxDynamicSharedMemorySize,
                             GEMM_SMEM_BYTES);
        attr_done = true;
    }

    // Zero the accumulation target (d_out is poisoned before timing)
    cudaMemsetAsync(d_out, 0, (size_t)out_size * sizeof(float), 0);

    gemm_kernel<<<(n_nodes + 127) / 128, 256, GEMM_SMEM_BYTES>>>(feature, norm, W, n_nodes);

    long long st = (long long)E * 8;
    scatter_kernel<<<(unsigned)((st + 255) / 256), 256>>>(src, dst, ediv, out, E, n_nodes);

    long long ft = (long long)n_nodes * (CAT_F / 4);
    finalize_kernel<<<(unsigned)((ft + 255) / 256), 256>>>(norm, out, n_nodes);
}

// round 5
// speedup vs baseline: 1.4333x; 1.4333x over previous
#include <cuda_runtime.h>
#include <cuda_fp16.h>
#include <cuda_bf16.h>
#include <cstdint>

#define N_NODES_MAX 100000
#define IN_F 128
#define OUT_F 64
#define NDIV 9
#define CAT_F (NDIV * OUT_F)   // 576
#define DPB 3                  // divisions per block

// Scratch: Wh[d][n][o] in fp16: 9*100000*64*2 = 115.2 MB
__device__ __half g_Whh[(size_t)NDIV * N_NODES_MAX * OUT_F];

// ---------------------------------------------------------------------------
// bf16 split helpers
// ---------------------------------------------------------------------------
__device__ __forceinline__ unsigned bf16bits(float x) {
    __nv_bfloat16 h = __float2bfloat16(x);           // round-to-nearest
    return (unsigned)__bfloat16_as_ushort(h);
}
// Split a K-pair (x0 -> low half, x1 -> high half) into hi/lo bf16x2 words.
__device__ __forceinline__ void split_pair(float x0, float x1,
                                           unsigned& hw, unsigned& lw) {
    unsigned h0 = bf16bits(x0), h1 = bf16bits(x1);
    float r0 = x0 - __uint_as_float(h0 << 16);
    float r1 = x1 - __uint_as_float(h1 << 16);
    unsigned l0 = bf16bits(r0), l1 = bf16bits(r1);
    hw = h0 | (h1 << 16);
    lw = l0 | (l1 << 16);
}

__device__ __forceinline__ void mma_bf16(float c[4],
                                         unsigned a0, unsigned a1, unsigned a2, unsigned a3,
                                         unsigned b0, unsigned b1) {
    asm volatile(
        "mma.sync.aligned.m16n8k16.row.col.f32.bf16.bf16.f32 "
        "{%0,%1,%2,%3}, {%4,%5,%6,%7}, {%8,%9}, {%0,%1,%2,%3};"
        : "+f"(c[0]), "+f"(c[1]), "+f"(c[2]), "+f"(c[3])
        : "r"(a0), "r"(a1), "r"(a2), "r"(a3), "r"(b0), "r"(b1));
}

// Fragment-packed smem layout, per row (128 K-elements = 64 bf16x2 pairs):
//   for k-chunk kc (16 K-elems = 8 pairs), pair u_local (0..7):
//   slot = (u_local&3)*4 + (u_local>>2)        -> hi word
//   slot + 2                                   -> lo word
//   word index in row = kc*16 + slot; row stride = 144 words (576 B),
//   144 % 32 == 16 -> paired-row LDS.128 phases are bank-conflict-free.
// Thread (g,t) fetches uint4 at row*144 + kc*16 + 4*t:
//   .x = hi(pair t), .y = hi(pair t+4), .z = lo(pair t), .w = lo(pair t+4)
// which is exactly the m16n8k16 (a0?,a2?) / (b0,b1) fragment pair.
#define ROW_W 144
#define A_WORDS (128 * ROW_W)
#define B_WORDS (64 * ROW_W)
#define GEMM_SMEM_BYTES ((A_WORDS + B_WORDS) * 4)   // 110,592 B

__device__ __forceinline__ int slot_of(int u_local) {
    return (u_local & 3) * 4 + (u_local >> 2);
}

__global__ __launch_bounds__(256, 2)
void gemm_kernel(const float* __restrict__ feature,
                 const float* __restrict__ norm,
                 const float* __restrict__ W,
                 int n_nodes) {
    extern __shared__ unsigned smw[];
    unsigned* As = smw;             // [128][ROW_W]
    unsigned* Bs = smw + A_WORDS;   // [64][ROW_W]

    const int row0 = blockIdx.x * 128;
    const int d0   = blockIdx.y * DPB;
    const int tid  = threadIdx.x;

    // Load + split A tile once (zero-pad past N). 128 rows x 32 float4.
    for (int i = tid; i < 128 * 32; i += 256) {
        int r = i >> 5, c4 = i & 31;
        float4 v = make_float4(0.f, 0.f, 0.f, 0.f);
        int gr = row0 + r;
        if (gr < n_nodes)
            v = *(const float4*)(feature + (size_t)gr * IN_F + c4 * 4);
        unsigned* rowp = As + r * ROW_W;
        int u0 = c4 * 2;                 // first pair index
        int kc0 = u0 >> 3, ul0 = u0 & 7;
        unsigned hw, lw;
        split_pair(v.x, v.y, hw, lw);
        int s0 = kc0 * 16 + slot_of(ul0);
        rowp[s0] = hw; rowp[s0 + 2] = lw;
        int u1 = u0 + 1;
        int kc1 = u1 >> 3, ul1 = u1 & 7;
        split_pair(v.z, v.w, hw, lw);
        int s1 = kc1 * 16 + slot_of(ul1);
        rowp[s1] = hw; rowp[s1 + 2] = lw;
    }

    const int warp = tid >> 5, lane = tid & 31;
    const int g = lane >> 2, t = lane & 3;
    const int m0 = warp * 16;
    const int r0 = row0 + m0 + g;
    const int r1 = r0 + 8;
    const float s0n = (r0 < n_nodes) ? __ldg(norm + r0) : 0.f;
    const float s1n = (r1 < n_nodes) ? __ldg(norm + r1) : 0.f;

    for (int dd = 0; dd < DPB; dd++) {
        const int d = d0 + dd;
        __syncthreads();   // protect Bs from previous iteration's readers
        // Load + split W_d into Bs. 64 rows x 32 float4.
        for (int i = tid; i < 64 * 32; i += 256) {
            int r = i >> 5, c4 = i & 31;
            float4 v = *(const float4*)(W + ((size_t)d * OUT_F + r) * IN_F + c4 * 4);
            unsigned* rowp = Bs + r * ROW_W;
            int u0 = c4 * 2;
            int kc0 = u0 >> 3, ul0 = u0 & 7;
            unsigned hw, lw;
            split_pair(v.x, v.y, hw, lw);
            int s0 = kc0 * 16 + slot_of(ul0);
            rowp[s0] = hw; rowp[s0 + 2] = lw;
            int u1 = u0 + 1;
            int kc1 = u1 >> 3, ul1 = u1 & 7;
            split_pair(v.z, v.w, hw, lw);
            int s1 = kc1 * 16 + slot_of(ul1);
            rowp[s1] = hw; rowp[s1 + 2] = lw;
        }
        __syncthreads();

        float acc[8][4];
#pragma unroll
        for (int nt = 0; nt < 8; nt++)
            acc[nt][0] = acc[nt][1] = acc[nt][2] = acc[nt][3] = 0.f;

#pragma unroll
        for (int kc = 0; kc < 8; kc++) {
            const int off = kc * 16 + 4 * t;
            uint4 ag  = *(const uint4*)(As + (m0 + g)     * ROW_W + off);
            uint4 ag8 = *(const uint4*)(As + (m0 + g + 8) * ROW_W + off);
#pragma unroll
            for (int nt = 0; nt < 8; nt++) {
                uint4 b = *(const uint4*)(Bs + (nt * 8 + g) * ROW_W + off);
                // 3-pass split: hi*hi + hi*lo + lo*hi
                mma_bf16(acc[nt], ag.x, ag8.x, ag.y, ag8.y, b.x, b.y);
                mma_bf16(acc[nt], ag.x, ag8.x, ag.y, ag8.y, b.z, b.w);
                mma_bf16(acc[nt], ag.z, ag8.z, ag.w, ag8.w, b.x, b.y);
            }
        }

        // Epilogue: scale by norm, store fp16
        __half* base = g_Whh + (size_t)d * n_nodes * OUT_F;
#pragma unroll
        for (int nt = 0; nt < 8; nt++) {
            int col = nt * 8 + 2 * t;
            if (r0 < n_nodes) {
                __half2 h = __floats2half2_rn(acc[nt][0] * s0n, acc[nt][1] * s0n);
                *(__half2*)(base + (size_t)r0 * OUT_F + col) = h;
            }
            if (r1 < n_nodes) {
                __half2 h = __floats2half2_rn(acc[nt][2] * s1n, acc[nt][3] * s1n);
                *(__half2*)(base + (size_t)r1 * OUT_F + col) = h;
            }
        }
    }
}

// ---------------------------------------------------------------------------
// Scatter: out[dst, div*64 + o] += Wh[div, src, o]
// 8 threads per edge: one uint4 (8 halves) gather + 2x red.global.add.v4.
// ---------------------------------------------------------------------------
__global__ __launch_bounds__(256)
void scatter_kernel(const int* __restrict__ src,
                    const int* __restrict__ dst,
                    const int* __restrict__ ediv,
                    float* __restrict__ out,
                    int E, int n_nodes) {
    long long tt = (long long)blockIdx.x * blockDim.x + threadIdx.x;
    long long total = (long long)E * 8;
    if (tt >= total) return;
    int e = (int)(tt >> 3);
    int j = (int)(tt & 7);
    int dv = __ldg(ediv + e);
    int s  = __ldg(src + e);
    int dd = __ldg(dst + e);
    const uint4 u = *(const uint4*)(g_Whh + ((size_t)dv * n_nodes + s) * OUT_F + j * 8);
    float2 f0 = __half22float2(*(const __half2*)&u.x);
    float2 f1 = __half22float2(*(const __half2*)&u.y);
    float2 f2 = __half22float2(*(const __half2*)&u.z);
    float2 f3 = __half22float2(*(const __half2*)&u.w);
    float* p = out + (size_t)dd * CAT_F + dv * OUT_F + j * 8;
    asm volatile("red.global.add.v4.f32 [%0], {%1,%2,%3,%4};"
                 :: "l"(p), "f"(f0.x), "f"(f0.y), "f"(f1.x), "f"(f1.y) : "memory");
    asm volatile("red.global.add.v4.f32 [%0], {%1,%2,%3,%4};"
                 :: "l"(p + 4), "f"(f2.x), "f"(f2.y), "f"(f3.x), "f"(f3.y) : "memory");
}

// ---------------------------------------------------------------------------
// Finalize: out = relu(out * norm[n]), in place. float4 per thread.
// ---------------------------------------------------------------------------
__global__ __launch_bounds__(256)
void finalize_kernel(const float* __restrict__ norm,
                     float* __restrict__ out,
                     int n_nodes) {
    long long tt = (long long)blockIdx.x * blockDim.x + threadIdx.x;
    long long total = (long long)n_nodes * (CAT_F / 4);
    if (tt >= total) return;
    int n = (int)(tt / (CAT_F / 4));
    float s = __ldg(norm + n);
    float4* p = (float4*)out + tt;
    float4 v = *p;
    v.x = fmaxf(v.x * s, 0.f);
    v.y = fmaxf(v.y * s, 0.f);
    v.z = fmaxf(v.z * s, 0.f);
    v.w = fmaxf(v.w * s, 0.f);
    *p = v;
}

// ---------------------------------------------------------------------------
extern "C" void kernel_launch(void* const* d_in, const int* in_sizes, int n_in,
                              void* d_out, int out_size) {
    const float* feature = (const float*)d_in[0];
    const float* norm    = (const float*)d_in[1];
    const float* W       = (const float*)d_in[2];
    const int*   src     = (const int*)d_in[3];
    const int*   dst     = (const int*)d_in[4];
    const int*   ediv    = (const int*)d_in[5];
    float* out = (float*)d_out;

    const int n_nodes = in_sizes[1];          // norm is [N,1]
    const int E       = in_sizes[3];          // src is [E]

    static bool attr_done = false;
    if (!attr_done) {
        cudaFuncSetAttribute(gemm_kernel, cudaFuncAttributeMaxDynamicSharedMemorySize,
                             GEMM_SMEM_BYTES);
        attr_done = true;
    }

    // Zero the accumulation target (d_out is poisoned before timing)
    cudaMemsetAsync(d_out, 0, (size_t)out_size * sizeof(float), 0);

    dim3 gg((n_nodes + 127) / 128, NDIV / DPB);
    gemm_kernel<<<gg, 256, GEMM_SMEM_BYTES>>>(feature, norm, W, n_nodes);

    long long st = (long long)E * 8;
    scatter_kernel<<<(unsigned)((st + 255) / 256), 256>>>(src, dst, ediv, out, E, n_nodes);

    long long ft = (long long)n_nodes * (CAT_F / 4);
    finalize_kernel<<<(unsigned)((ft + 255) / 256), 256>>>(norm, out, n_nodes);
}

// round 6
// speedup vs baseline: 1.5109x; 1.0542x over previous
#include <cuda_runtime.h>
#include <cuda_fp16.h>
#include <cuda_bf16.h>
#include <cstdint>

#define N_NODES_MAX 100000
#define E_MAX 1600000
#define IN_F 128
#define OUT_F 64
#define NDIV 9
#define CAT_F (NDIV * OUT_F)   // 576
#define DPB 3                  // divisions per block (GEMM)
#define NB_MAX (N_NODES_MAX * NDIV)   // 900000 buckets

// Scratch (static device globals: allowed)
__device__ __half  g_Whh[(size_t)NDIV * N_NODES_MAX * OUT_F];  // 115.2 MB
__device__ int     g_hist[NB_MAX];
__device__ int     g_offs[NB_MAX + 1];
__device__ int     g_cursor[NB_MAX];
__device__ int     g_bsums[1024];
__device__ int     g_meta[E_MAX];      // src node per sorted edge slot

// ---------------------------------------------------------------------------
// bf16 split helpers
// ---------------------------------------------------------------------------
__device__ __forceinline__ unsigned bf16bits(float x) {
    __nv_bfloat16 h = __float2bfloat16(x);
    return (unsigned)__bfloat16_as_ushort(h);
}
__device__ __forceinline__ void split_pair(float x0, float x1,
                                           unsigned& hw, unsigned& lw) {
    unsigned h0 = bf16bits(x0), h1 = bf16bits(x1);
    float r0 = x0 - __uint_as_float(h0 << 16);
    float r1 = x1 - __uint_as_float(h1 << 16);
    unsigned l0 = bf16bits(r0), l1 = bf16bits(r1);
    hw = h0 | (h1 << 16);
    lw = l0 | (l1 << 16);
}

__device__ __forceinline__ void mma_bf16(float c[4],
                                         unsigned a0, unsigned a1, unsigned a2, unsigned a3,
                                         unsigned b0, unsigned b1) {
    asm volatile(
        "mma.sync.aligned.m16n8k16.row.col.f32.bf16.bf16.f32 "
        "{%0,%1,%2,%3}, {%4,%5,%6,%7}, {%8,%9}, {%0,%1,%2,%3};"
        : "+f"(c[0]), "+f"(c[1]), "+f"(c[2]), "+f"(c[3])
        : "r"(a0), "r"(a1), "r"(a2), "r"(a3), "r"(b0), "r"(b1));
}

// Fragment-packed smem layout (see R4): per row, k-chunk kc, pair u_local:
// slot = (u&3)*4 + (u>>2) -> hi word; slot+2 -> lo word; word = kc*16+slot.
#define ROW_W 144
#define A_WORDS (128 * ROW_W)
#define B_WORDS (64 * ROW_W)
#define GEMM_SMEM_BYTES ((A_WORDS + B_WORDS) * 4)   // 110,592 B

__device__ __forceinline__ int slot_of(int u_local) {
    return (u_local & 3) * 4 + (u_local >> 2);
}

__global__ __launch_bounds__(256, 2)
void gemm_kernel(const float* __restrict__ feature,
                 const float* __restrict__ norm,
                 const float* __restrict__ W,
                 int n_nodes) {
    extern __shared__ unsigned smw[];
    unsigned* As = smw;             // [128][ROW_W]
    unsigned* Bs = smw + A_WORDS;   // [64][ROW_W]

    const int row0 = blockIdx.x * 128;
    const int d0   = blockIdx.y * DPB;
    const int tid  = threadIdx.x;

    // Load + split A tile once (zero-pad past N). 128 rows x 32 float4.
    for (int i = tid; i < 128 * 32; i += 256) {
        int r = i >> 5, c4 = i & 31;
        float4 v = make_float4(0.f, 0.f, 0.f, 0.f);
        int gr = row0 + r;
        if (gr < n_nodes)
            v = *(const float4*)(feature + (size_t)gr * IN_F + c4 * 4);
        unsigned* rowp = As + r * ROW_W;
        int u0 = c4 * 2;
        unsigned hw, lw;
        split_pair(v.x, v.y, hw, lw);
        int s0 = (u0 >> 3) * 16 + slot_of(u0 & 7);
        rowp[s0] = hw; rowp[s0 + 2] = lw;
        int u1 = u0 + 1;
        split_pair(v.z, v.w, hw, lw);
        int s1 = (u1 >> 3) * 16 + slot_of(u1 & 7);
        rowp[s1] = hw; rowp[s1 + 2] = lw;
    }

    const int warp = tid >> 5, lane = tid & 31;
    const int g = lane >> 2, t = lane & 3;
    const int m0 = warp * 16;
    const int r0 = row0 + m0 + g;
    const int r1 = r0 + 8;
    const float s0n = (r0 < n_nodes) ? __ldg(norm + r0) : 0.f;
    const float s1n = (r1 < n_nodes) ? __ldg(norm + r1) : 0.f;

    for (int dd = 0; dd < DPB; dd++) {
        const int d = d0 + dd;
        __syncthreads();
        for (int i = tid; i < 64 * 32; i += 256) {
            int r = i >> 5, c4 = i & 31;
            float4 v = *(const float4*)(W + ((size_t)d * OUT_F + r) * IN_F + c4 * 4);
            unsigned* rowp = Bs + r * ROW_W;
            int u0 = c4 * 2;
            unsigned hw, lw;
            split_pair(v.x, v.y, hw, lw);
            int s0 = (u0 >> 3) * 16 + slot_of(u0 & 7);
            rowp[s0] = hw; rowp[s0 + 2] = lw;
            int u1 = u0 + 1;
            split_pair(v.z, v.w, hw, lw);
            int s1 = (u1 >> 3) * 16 + slot_of(u1 & 7);
            rowp[s1] = hw; rowp[s1 + 2] = lw;
        }
        __syncthreads();

        float acc[8][4];
#pragma unroll
        for (int nt = 0; nt < 8; nt++)
            acc[nt][0] = acc[nt][1] = acc[nt][2] = acc[nt][3] = 0.f;

#pragma unroll
        for (int kc = 0; kc < 8; kc++) {
            const int off = kc * 16 + 4 * t;
            uint4 ag  = *(const uint4*)(As + (m0 + g)     * ROW_W + off);
            uint4 ag8 = *(const uint4*)(As + (m0 + g + 8) * ROW_W + off);
            uint4 b[8];
#pragma unroll
            for (int nt = 0; nt < 8; nt++)
                b[nt] = *(const uint4*)(Bs + (nt * 8 + g) * ROW_W + off);
            // pass-outer: consecutive MMAs hit different accumulators
#pragma unroll
            for (int nt = 0; nt < 8; nt++)
                mma_bf16(acc[nt], ag.x, ag8.x, ag.y, ag8.y, b[nt].x, b[nt].y);
#pragma unroll
            for (int nt = 0; nt < 8; nt++)
                mma_bf16(acc[nt], ag.x, ag8.x, ag.y, ag8.y, b[nt].z, b[nt].w);
#pragma unroll
            for (int nt = 0; nt < 8; nt++)
                mma_bf16(acc[nt], ag.z, ag8.z, ag.w, ag8.w, b[nt].x, b[nt].y);
        }

        __half* base = g_Whh + (size_t)d * n_nodes * OUT_F;
#pragma unroll
        for (int nt = 0; nt < 8; nt++) {
            int col = nt * 8 + 2 * t;
            if (r0 < n_nodes) {
                __half2 h = __floats2half2_rn(acc[nt][0] * s0n, acc[nt][1] * s0n);
                *(__half2*)(base + (size_t)r0 * OUT_F + col) = h;
            }
            if (r1 < n_nodes) {
                __half2 h = __floats2half2_rn(acc[nt][2] * s1n, acc[nt][3] * s1n);
                *(__half2*)(base + (size_t)r1 * OUT_F + col) = h;
            }
        }
    }
}

// ---------------------------------------------------------------------------
// Edge bucketing: bucket = dst * 9 + div
// ---------------------------------------------------------------------------
__global__ __launch_bounds__(256)
void hist_kernel(const int* __restrict__ dst, const int* __restrict__ ediv, int E) {
    int e = blockIdx.x * blockDim.x + threadIdx.x;
    if (e >= E) return;
    atomicAdd(&g_hist[dst[e] * NDIV + ediv[e]], 1);
}

__device__ __forceinline__ int block_scan_1024(int v, int tid, int* ws) {
    // returns inclusive scan over the 1024-thread block
    int lane = tid & 31, wid = tid >> 5;
    int x = v;
#pragma unroll
    for (int o = 1; o < 32; o <<= 1) {
        int y = __shfl_up_sync(0xFFFFFFFFu, x, o);
        if (lane >= o) x += y;
    }
    if (lane == 31) ws[wid] = x;
    __syncthreads();
    if (wid == 0) {
        int s = ws[lane];
#pragma unroll
        for (int o = 1; o < 32; o <<= 1) {
            int y = __shfl_up_sync(0xFFFFFFFFu, s, o);
            if (lane >= o) s += y;
        }
        ws[lane] = s;
    }
    __syncthreads();
    return x + (wid > 0 ? ws[wid - 1] : 0);
}

__global__ __launch_bounds__(1024)
void scan_l1(int NB) {
    __shared__ int ws[32];
    int i = blockIdx.x * 1024 + threadIdx.x;
    int v = (i < NB) ? g_hist[i] : 0;
    int incl = block_scan_1024(v, threadIdx.x, ws);
    if (i <= NB) g_offs[i] = incl - v;   // block-local exclusive
    if (threadIdx.x == 1023) g_bsums[blockIdx.x] = incl;
}

__global__ __launch_bounds__(1024)
void scan_l2(int nblk) {
    __shared__ int ws[32];
    int v = (threadIdx.x < nblk) ? g_bsums[threadIdx.x] : 0;
    int incl = block_scan_1024(v, threadIdx.x, ws);
    if (threadIdx.x < nblk) g_bsums[threadIdx.x] = incl - v;  // exclusive
}

__global__ __launch_bounds__(1024)
void scan_l3(int NB, int E) {
    int i = blockIdx.x * 1024 + threadIdx.x;
    if (i < NB) {
        int o = g_offs[i] + g_bsums[blockIdx.x];
        g_offs[i] = o;
        g_cursor[i] = o;
    }
    if (i == NB) g_offs[NB] = E;
}

__global__ __launch_bounds__(256)
void reorder_kernel(const int* __restrict__ src, const int* __restrict__ dst,
                    const int* __restrict__ ediv, int E) {
    int e = blockIdx.x * blockDim.x + threadIdx.x;
    if (e >= E) return;
    int b = dst[e] * NDIV + ediv[e];
    int pos = atomicAdd(&g_cursor[b], 1);
    g_meta[pos] = src[e];
}

// ---------------------------------------------------------------------------
// Accumulate: one warp per (dst, div). Lane owns 2 output floats in regs.
// Gathers fp16 Wh rows (128 B coalesced per edge), applies norm*relu, writes
// 256 B coalesced. Writes EVERY bucket (zeros incl.) -> no memset/finalize.
// ---------------------------------------------------------------------------
__global__ __launch_bounds__(256)
void accum_kernel(const float* __restrict__ norm,
                  float* __restrict__ out,
                  int n_nodes) {
    int w = blockIdx.x * 8 + (threadIdx.x >> 5);   // bucket id
    int NB = n_nodes * NDIV;
    if (w >= NB) return;
    int lane = threadIdx.x & 31;
    int d  = w - (w / NDIV) * NDIV;
    int dn = w / NDIV;

    int start = __ldg(g_offs + w);
    int end   = __ldg(g_offs + w + 1);

    float2 acc = make_float2(0.f, 0.f);
    const __half* base = g_Whh + (size_t)d * n_nodes * OUT_F + 2 * lane;
    for (int e = start; e < end; e++) {
        int s = __ldg(g_meta + e);
        __half2 h = *(const __half2*)(base + (size_t)s * OUT_F);
        float2 f = __half22float2(h);
        acc.x += f.x;
        acc.y += f.y;
    }
    float nr = __ldg(norm + dn);
    float2 o;
    o.x = fmaxf(acc.x * nr, 0.f);
    o.y = fmaxf(acc.y * nr, 0.f);
    *(float2*)(out + (size_t)dn * CAT_F + d * OUT_F + 2 * lane) = o;
}

// ---------------------------------------------------------------------------
extern "C" void kernel_launch(void* const* d_in, const int* in_sizes, int n_in,
                              void* d_out, int out_size) {
    const float* feature = (const float*)d_in[0];
    const float* norm    = (const float*)d_in[1];
    const float* W       = (const float*)d_in[2];
    const int*   src     = (const int*)d_in[3];
    const int*   dst     = (const int*)d_in[4];
    const int*   ediv    = (const int*)d_in[5];
    float* out = (float*)d_out;

    const int n_nodes = in_sizes[1];          // norm is [N,1]
    const int E       = in_sizes[3];          // src is [E]
    const int NB      = n_nodes * NDIV;

    static void* hist_ptr = nullptr;
    static bool attr_done = false;
    if (!attr_done) {
        cudaFuncSetAttribute(gemm_kernel, cudaFuncAttributeMaxDynamicSharedMemorySize,
                             GEMM_SMEM_BYTES);
        cudaGetSymbolAddress(&hist_ptr, g_hist);
        attr_done = true;
    }

    // Zero the bucket histogram (re-done every call; graph-replay safe)
    cudaMemsetAsync(hist_ptr, 0, (size_t)NB * sizeof(int), 0);

    dim3 gg((n_nodes + 127) / 128, NDIV / DPB);
    gemm_kernel<<<gg, 256, GEMM_SMEM_BYTES>>>(feature, norm, W, n_nodes);

    int eb = (E + 255) / 256;
    hist_kernel<<<eb, 256>>>(dst, ediv, E);

    int nblk1 = (NB + 1023) / 1024;
    scan_l1<<<nblk1, 1024>>>(NB);
    scan_l2<<<1, 1024>>>(nblk1);
    scan_l3<<<nblk1 + 1, 1024>>>(NB, E);   // +1 block covers i == NB

    reorder_kernel<<<eb, 256>>>(src, dst, ediv, E);

    int ab = (NB + 7) / 8;
    accum_kernel<<<ab, 256>>>(norm, out, n_nodes);
}